// round 14
// baseline (speedup 1.0000x reference)
#include <cuda_runtime.h>
#include <cuda_fp16.h>
#include <cstdint>

#define N_NODES 4096
#define IN_F    128
#define HEADS   8
#define HIDDEN  8
#define OUTF    64   // HEADS*HIDDEN
#define SLOPE   0.2f
#define NODES_PER_PROJ 16
#define PROJ_BLOCKS (N_NODES / NODES_PER_PROJ)     // 256
#define COMP_BLOCKS 2048                            // 8 warps x 1024 words each
#define ATTN_BLOCKS (N_NODES / 4)                   // 1024
#define MAXEH   96            // max edges per half-row (Poisson(41), max ~75)

// Scratch (allocation-free rule: __device__ globals)
__device__ __half2 g_half[N_NODES * (OUTF / 2)];      // 512 KB fp16 features
__device__ float g_sl[N_NODES * HEADS];               // 128 KB
__device__ float g_sr[N_NODES * HEADS];               // 128 KB
__device__ unsigned int g_bits[N_NODES * N_NODES / 32]; // 2 MB bitmask (lane-packed order)

// Producer->consumer sync state (zero-init; every launch leaves it zeroed)
__device__ int g_flag[COMP_BLOCKS];   // set by compress block, cleared by its attn consumer
__device__ int g_projdone;            // proj blocks completed
__device__ int g_attndone;            // attn blocks completed (last one resets counters)

// ---------------------------------------------------------------------------
// ONE fused kernel, heterogeneous grid:
//   [0, 256):      proj   g = h @ W + sl/sr head dots (fp16 feature table)
//   [256, 2304):   compress  64 MB int32 adjacency -> 2 MB bitmask
//   [2304, 3328):  attn   4 rows/block, gated on its 2 compress flags + proj
// Deadlock-free: consumers (1024 blocks) < resident capacity (~1184), and
// producer bids precede consumer bids, so producers always make progress.
// Bitmask packing (ballot-free): g_bits[wg*32 + lane] bit (4c+wi) <->
//   node wg*1024 + c*128 + lane*4 + wi
// ---------------------------------------------------------------------------
__global__ void __launch_bounds__(256) fused_kernel(
    const float* __restrict__ h,
    const unsigned int* __restrict__ adj,
    const float* __restrict__ W,
    const float* __restrict__ a_l,
    const float* __restrict__ a_r,
    float* __restrict__ out)
{
    __shared__ float hs[NODES_PER_PROJ][IN_F];      // 8 KB (proj)
    __shared__ float gs[NODES_PER_PROJ][OUTF];      // 4 KB (proj)
    __shared__ uint16_t lists[8][MAXEH];            // 1.5 KB (attn)
    __shared__ float part_acc[8][OUTF];             // 2 KB (attn)
    __shared__ float part_den[8][HEADS];            // 256 B (attn)

    const int tid = threadIdx.x;
    const int bid = blockIdx.x;

    if (bid < PROJ_BLOCKS) {
        // ================= proj =================
        const int node0 = bid * NODES_PER_PROJ;

        for (int i = tid; i < NODES_PER_PROJ * IN_F; i += 256)
            hs[i >> 7][i & 127] = h[(size_t)node0 * IN_F + i];
        __syncthreads();

        const int c  = tid & 63;
        const int nb = (tid >> 6) * 4;
        float acc[4] = {0.f, 0.f, 0.f, 0.f};
        #pragma unroll 8
        for (int k = 0; k < IN_F; k++) {
            const float wv = __ldg(&W[k * OUTF + c]);
            acc[0] = fmaf(hs[nb + 0][k], wv, acc[0]);
            acc[1] = fmaf(hs[nb + 1][k], wv, acc[1]);
            acc[2] = fmaf(hs[nb + 2][k], wv, acc[2]);
            acc[3] = fmaf(hs[nb + 3][k], wv, acc[3]);
        }
        __half* gh = reinterpret_cast<__half*>(g_half);
        #pragma unroll
        for (int q = 0; q < 4; q++) {
            gh[(size_t)(node0 + nb + q) * OUTF + c] = __float2half(acc[q]);
            gs[nb + q][c] = acc[q];
        }
        __syncthreads();

        const int t = tid & 127;
        const int nl = t >> 3, hh = t & 7;
        const float* av = (tid < 128) ? a_l : a_r;
        float s = 0.f;
        #pragma unroll
        for (int d = 0; d < 8; d++) s = fmaf(gs[nl][hh * 8 + d], av[d], s);
        if (tid < 128) g_sl[(node0 + nl) * HEADS + hh] = s;
        else           g_sr[(node0 + nl) * HEADS + hh] = s;

        __threadfence();
        __syncthreads();
        if (tid == 0) atomicAdd(&g_projdone, 1);
        return;
    }

    if (bid < PROJ_BLOCKS + COMP_BLOCKS) {
        // ================= compress =================
        const int cb = bid - PROJ_BLOCKS;
        const int lane = tid & 31;
        const size_t warp_global = ((size_t)cb * 256 + tid) >> 5;
        const size_t word_base = warp_global * 1024;

        const uint4* p = reinterpret_cast<const uint4*>(adj) + word_base / 4;
        uint4 v[8];
        #pragma unroll
        for (int c = 0; c < 8; c++) v[c] = __ldcs(p + c * 32 + lane);

        unsigned w = 0u;
        #pragma unroll
        for (int c = 0; c < 8; c++) {
            w |= (v[c].x != 0u ? 1u : 0u) << (4 * c + 0);
            w |= (v[c].y != 0u ? 1u : 0u) << (4 * c + 1);
            w |= (v[c].z != 0u ? 1u : 0u) << (4 * c + 2);
            w |= (v[c].w != 0u ? 1u : 0u) << (4 * c + 3);
        }
        g_bits[warp_global * 32 + lane] = w;

        __threadfence();
        __syncthreads();
        if (tid == 0) atomicExch(&g_flag[cb], 1);
        return;
    }

    // ================= attn (4 rows per block) =================
    const int ab = bid - (PROJ_BLOCKS + COMP_BLOCKS);

    // Gate on producers: all proj + this block's two compress blocks.
    if (tid == 0) {
        volatile int* pd = &g_projdone;
        while (*pd < PROJ_BLOCKS) __nanosleep(64);
        volatile int* f0 = &g_flag[2 * ab];
        while (*f0 == 0) __nanosleep(64);
        volatile int* f1 = &g_flag[2 * ab + 1];
        while (*f1 == 0) __nanosleep(64);
        __threadfence();
    }
    __syncthreads();

    const int warp = tid >> 5;
    const int lane = tid & 31;
    const int rloc = warp >> 1;
    const int half = warp & 1;
    const int row  = ab * 4 + rloc;

    uint16_t* list = lists[warp];
    const int side  = lane >> 4;
    const int sub   = lane & 15;
    const int headp = sub >> 1;
    const float sl_h = g_sl[row * HEADS + headp];

    // ---- Load half bitmask row (2 words/lane) and compact ----
    const uint2 mv = reinterpret_cast<const uint2*>(
        g_bits + row * 128 + half * 64)[lane];
    const int myc = __popc(mv.x) + __popc(mv.y);
    int off = myc;
    #pragma unroll
    for (int d = 1; d < 32; d <<= 1) {
        int n = __shfl_up_sync(0xFFFFFFFFu, off, d);
        if (lane >= d) off += n;
    }
    const int cnt = __shfl_sync(0xFFFFFFFFu, off, 31);
    off -= myc;
    {
        unsigned ws[2] = {mv.x, mv.y};
        #pragma unroll
        for (int wi = 0; wi < 2; wi++) {
            unsigned m = ws[wi];
            const int widx = half * 64 + lane * 2 + wi;
            const int jb = (widx >> 5) * 1024 + (widx & 31) * 4;
            while (m) {
                const int b = __ffs(m) - 1;
                m &= m - 1;
                list[off++] = (uint16_t)(jb + ((b >> 2) << 7) + (b & 3));
            }
        }
    }
    __syncwarp();

    // ---- Edge loop: 8 edges per iteration (4 per side), batched loads ----
    float acc0 = 0.f, acc1 = 0.f, acc2 = 0.f, acc3 = 0.f, den = 0.f;
    int k = 0;
    #pragma unroll 1
    for (; k + 8 <= cnt; k += 8) {
        int j[4];
        #pragma unroll
        for (int q = 0; q < 4; q++) j[q] = list[k + q * 2 + side];
        uint2 hv[4];
        float sr[4];
        #pragma unroll
        for (int q = 0; q < 4; q++) {
            hv[q] = *reinterpret_cast<const uint2*>(
                g_half + j[q] * (OUTF / 2) + sub * 2);
            sr[q] = g_sr[j[q] * HEADS + headp];
        }
        #pragma unroll
        for (int q = 0; q < 4; q++) {
            float e = sl_h + sr[q];
            e = fmaxf(e, SLOPE * e);
            const float w = __expf(e);
            den += w;
            const float2 ga = __half22float2(*reinterpret_cast<const __half2*>(&hv[q].x));
            const float2 gb = __half22float2(*reinterpret_cast<const __half2*>(&hv[q].y));
            acc0 = fmaf(w, ga.x, acc0);
            acc1 = fmaf(w, ga.y, acc1);
            acc2 = fmaf(w, gb.x, acc2);
            acc3 = fmaf(w, gb.y, acc3);
        }
    }
    #pragma unroll 1
    for (; k + 2 <= cnt; k += 2) {
        const int j = list[k + side];
        const uint2 hv = *reinterpret_cast<const uint2*>(
            g_half + j * (OUTF / 2) + sub * 2);
        const float srj = g_sr[j * HEADS + headp];
        float e = sl_h + srj;
        e = fmaxf(e, SLOPE * e);
        const float w = __expf(e);
        den += w;
        const float2 ga = __half22float2(*reinterpret_cast<const __half2*>(&hv.x));
        const float2 gb = __half22float2(*reinterpret_cast<const __half2*>(&hv.y));
        acc0 = fmaf(w, ga.x, acc0);
        acc1 = fmaf(w, ga.y, acc1);
        acc2 = fmaf(w, gb.x, acc2);
        acc3 = fmaf(w, gb.y, acc3);
    }
    if (k < cnt && side == 0) {
        const int j = list[k];
        const uint2 hv = *reinterpret_cast<const uint2*>(
            g_half + j * (OUTF / 2) + sub * 2);
        const float srj = g_sr[j * HEADS + headp];
        float e = sl_h + srj;
        e = fmaxf(e, SLOPE * e);
        const float w = __expf(e);
        den += w;
        const float2 ga = __half22float2(*reinterpret_cast<const __half2*>(&hv.x));
        const float2 gb = __half22float2(*reinterpret_cast<const __half2*>(&hv.y));
        acc0 = fmaf(w, ga.x, acc0);
        acc1 = fmaf(w, ga.y, acc1);
        acc2 = fmaf(w, gb.x, acc2);
        acc3 = fmaf(w, gb.y, acc3);
    }

    // ---- Combine the two 16-lane sides, stash per-warp partials ----
    acc0 += __shfl_down_sync(0xFFFFFFFFu, acc0, 16);
    acc1 += __shfl_down_sync(0xFFFFFFFFu, acc1, 16);
    acc2 += __shfl_down_sync(0xFFFFFFFFu, acc2, 16);
    acc3 += __shfl_down_sync(0xFFFFFFFFu, acc3, 16);
    den  += __shfl_down_sync(0xFFFFFFFFu, den, 16);

    if (lane < 16) {
        part_acc[warp][sub * 4 + 0] = acc0;
        part_acc[warp][sub * 4 + 1] = acc1;
        part_acc[warp][sub * 4 + 2] = acc2;
        part_acc[warp][sub * 4 + 3] = acc3;
        if ((sub & 1) == 0) part_den[warp][headp] = den;
    }
    __syncthreads();

    // ---- Final: 256 threads cover 4 rows x 64 feats ----
    {
        const int r = tid >> 6;
        const int f = tid & 63;
        const float s = part_acc[2 * r][f] + part_acc[2 * r + 1][f];
        const int hh = f >> 3;
        const float d = part_den[2 * r][hh] + part_den[2 * r + 1][hh];
        out[(size_t)(ab * 4 + r) * OUTF + f] = s / d;
    }

    // ---- Replay hygiene: clear this block's flags; last block resets ----
    if (tid == 0) {
        g_flag[2 * ab] = 0;
        g_flag[2 * ab + 1] = 0;
        __threadfence();
        const int prev = atomicAdd(&g_attndone, 1);
        if (prev == ATTN_BLOCKS - 1) {
            g_projdone = 0;
            g_attndone = 0;
        }
    }
}

// ---------------------------------------------------------------------------
extern "C" void kernel_launch(void* const* d_in, const int* in_sizes, int n_in,
                              void* d_out, int out_size)
{
    const float*        h   = (const float*)d_in[0];
    const unsigned int* adj = (const unsigned int*)d_in[1];
    const float*        W   = (const float*)d_in[2];
    const float*        a_l = (const float*)d_in[3];
    const float*        a_r = (const float*)d_in[4];
    float*              out = (float*)d_out;

    fused_kernel<<<PROJ_BLOCKS + COMP_BLOCKS + ATTN_BLOCKS, 256>>>(
        h, adj, W, a_l, a_r, out);
}

// round 15
// speedup vs baseline: 1.0339x; 1.0339x over previous
#include <cuda_runtime.h>
#include <cuda_fp16.h>
#include <cstdint>

#define N_NODES 4096
#define IN_F    128
#define HEADS   8
#define HIDDEN  8
#define OUTF    64   // HEADS*HIDDEN
#define SLOPE   0.2f
#define NODES_PER_PROJ 16
#define PROJ_BLOCKS (N_NODES / NODES_PER_PROJ)     // 256
#define FUSE_BLOCKS (N_NODES / 2)                   // 2048: 2 rows per block
#define MAXEQ   64            // max edges per 1024-node quarter (mean ~20, max ~48)

// Scratch (allocation-free rule: __device__ globals)
__device__ __half2 g_half[N_NODES * (OUTF / 2)];      // 512 KB fp16 features
__device__ float g_sl[N_NODES * HEADS];               // 128 KB
__device__ float g_sr[N_NODES * HEADS];               // 128 KB

// Sync state (zero-init; every launch leaves it zeroed again)
__device__ int g_projdone;   // proj blocks completed
__device__ int g_fusedone;   // fused blocks completed (last one resets)

// ---------------------------------------------------------------------------
// ONE kernel, heterogeneous grid:
//   [0, 256):      proj  g = h @ W + sl/sr head dots (fp16 feature table)
//   [256, 2304):   fused compress+attn — each block owns 2 adjacency rows.
//     Per warp (8/block): stream its quarter-row (1024 words, 8 front-batched
//     LDG.128/lane, __ldcs), pack to a 32-bit mask IN REGISTERS (no bitmask
//     array, no inter-block flags), compact to a ~20-edge smem list, gate on
//     proj, then run the x4-batched edge loop. 4 warps/row combine in smem.
// The adjacency load + compaction don't depend on proj, so the proj gate is
// reached only after ~all of the warp's memory latency — near-zero spin.
// Single-pass softmax exact (|e| < ~3 in fp32); fp16 features add ~1e-4 err.
// ---------------------------------------------------------------------------
__global__ void __launch_bounds__(256) fused_kernel(
    const float* __restrict__ h,
    const unsigned int* __restrict__ adj,
    const float* __restrict__ W,
    const float* __restrict__ a_l,
    const float* __restrict__ a_r,
    float* __restrict__ out)
{
    __shared__ float hs[NODES_PER_PROJ][IN_F];      // 8 KB (proj)
    __shared__ float gs[NODES_PER_PROJ][OUTF];      // 4 KB (proj)
    __shared__ uint16_t lists[8][MAXEQ];            // 1 KB (attn)
    __shared__ float part_acc[8][OUTF];             // 2 KB (attn)
    __shared__ float part_den[8][HEADS];            // 256 B (attn)

    const int tid = threadIdx.x;
    const int bid = blockIdx.x;

    if (bid < PROJ_BLOCKS) {
        // ================= proj =================
        const int node0 = bid * NODES_PER_PROJ;

        for (int i = tid; i < NODES_PER_PROJ * IN_F; i += 256)
            hs[i >> 7][i & 127] = h[(size_t)node0 * IN_F + i];
        __syncthreads();

        const int c  = tid & 63;
        const int nb = (tid >> 6) * 4;
        float acc[4] = {0.f, 0.f, 0.f, 0.f};
        #pragma unroll 8
        for (int k = 0; k < IN_F; k++) {
            const float wv = __ldg(&W[k * OUTF + c]);
            acc[0] = fmaf(hs[nb + 0][k], wv, acc[0]);
            acc[1] = fmaf(hs[nb + 1][k], wv, acc[1]);
            acc[2] = fmaf(hs[nb + 2][k], wv, acc[2]);
            acc[3] = fmaf(hs[nb + 3][k], wv, acc[3]);
        }
        __half* gh = reinterpret_cast<__half*>(g_half);
        #pragma unroll
        for (int q = 0; q < 4; q++) {
            gh[(size_t)(node0 + nb + q) * OUTF + c] = __float2half(acc[q]);
            gs[nb + q][c] = acc[q];
        }
        __syncthreads();

        const int t = tid & 127;
        const int nl = t >> 3, hh = t & 7;
        const float* av = (tid < 128) ? a_l : a_r;
        float s = 0.f;
        #pragma unroll
        for (int d = 0; d < 8; d++) s = fmaf(gs[nl][hh * 8 + d], av[d], s);
        if (tid < 128) g_sl[(node0 + nl) * HEADS + hh] = s;
        else           g_sr[(node0 + nl) * HEADS + hh] = s;

        __threadfence();
        __syncthreads();
        if (tid == 0) atomicAdd(&g_projdone, 1);
        return;
    }

    // ================= fused compress + attn (2 rows per block) =================
    const int fb   = bid - PROJ_BLOCKS;
    const int warp = tid >> 5;
    const int lane = tid & 31;
    const int rloc = warp >> 2;             // 0..1: row within block
    const int q    = warp & 3;              // 0..3: quarter of the row
    const int row  = fb * 2 + rloc;

    // ---- Stream this warp's quarter-row: 8 front-batched LDG.128 ----
    const uint4* p = reinterpret_cast<const uint4*>(adj) +
                     ((size_t)row * 4096 + q * 1024) / 4;
    uint4 v[8];
    #pragma unroll
    for (int c = 0; c < 8; c++) v[c] = __ldcs(p + c * 32 + lane);

    // ---- Pack to one 32-bit mask per lane (bit 4c+wi <-> node q*1024+c*128+lane*4+wi)
    unsigned m = 0u;
    #pragma unroll
    for (int c = 0; c < 8; c++) {
        m |= (v[c].x != 0u ? 1u : 0u) << (4 * c + 0);
        m |= (v[c].y != 0u ? 1u : 0u) << (4 * c + 1);
        m |= (v[c].z != 0u ? 1u : 0u) << (4 * c + 2);
        m |= (v[c].w != 0u ? 1u : 0u) << (4 * c + 3);
    }

    // ---- Compact: popc + prefix scan + bit-walk into smem list ----
    uint16_t* list = lists[warp];
    const int myc = __popc(m);
    int off = myc;
    #pragma unroll
    for (int d = 1; d < 32; d <<= 1) {
        int n = __shfl_up_sync(0xFFFFFFFFu, off, d);
        if (lane >= d) off += n;
    }
    const int cnt = __shfl_sync(0xFFFFFFFFu, off, 31);
    off -= myc;                                  // exclusive prefix
    {
        const int jb = q * 1024 + lane * 4;
        unsigned mm = m;
        while (mm) {
            const int b = __ffs(mm) - 1;
            mm &= mm - 1;
            list[off++] = (uint16_t)(jb + ((b >> 2) << 7) + (b & 3));
        }
    }
    __syncwarp();

    // ---- Gate on proj (reached after all load latency -> near-zero spin) ----
    if (tid == 0) {
        volatile int* pd = &g_projdone;
        while (*pd < PROJ_BLOCKS) __nanosleep(32);
        __threadfence();
    }
    __syncthreads();

    const int side  = lane >> 4;          // 0: even edges, 1: odd edges
    const int sub   = lane & 15;          // lane within edge group
    const int headp = sub >> 1;           // this lane's head
    const float sl_h = g_sl[row * HEADS + headp];

    // ---- Edge loop: 8 edges per iteration (4 per side), batched loads ----
    float acc0 = 0.f, acc1 = 0.f, acc2 = 0.f, acc3 = 0.f, den = 0.f;
    int k = 0;
    #pragma unroll 1
    for (; k + 8 <= cnt; k += 8) {
        int j[4];
        #pragma unroll
        for (int qq = 0; qq < 4; qq++) j[qq] = list[k + qq * 2 + side];
        uint2 hv[4];
        float sr[4];
        #pragma unroll
        for (int qq = 0; qq < 4; qq++) {
            hv[qq] = *reinterpret_cast<const uint2*>(
                g_half + j[qq] * (OUTF / 2) + sub * 2);
            sr[qq] = g_sr[j[qq] * HEADS + headp];
        }
        #pragma unroll
        for (int qq = 0; qq < 4; qq++) {
            float e = sl_h + sr[qq];
            e = fmaxf(e, SLOPE * e);
            const float w = __expf(e);
            den += w;
            const float2 ga = __half22float2(*reinterpret_cast<const __half2*>(&hv[qq].x));
            const float2 gb = __half22float2(*reinterpret_cast<const __half2*>(&hv[qq].y));
            acc0 = fmaf(w, ga.x, acc0);
            acc1 = fmaf(w, ga.y, acc1);
            acc2 = fmaf(w, gb.x, acc2);
            acc3 = fmaf(w, gb.y, acc3);
        }
    }
    #pragma unroll 1
    for (; k + 2 <= cnt; k += 2) {
        const int j = list[k + side];
        const uint2 hv = *reinterpret_cast<const uint2*>(
            g_half + j * (OUTF / 2) + sub * 2);
        const float srj = g_sr[j * HEADS + headp];
        float e = sl_h + srj;
        e = fmaxf(e, SLOPE * e);
        const float w = __expf(e);
        den += w;
        const float2 ga = __half22float2(*reinterpret_cast<const __half2*>(&hv.x));
        const float2 gb = __half22float2(*reinterpret_cast<const __half2*>(&hv.y));
        acc0 = fmaf(w, ga.x, acc0);
        acc1 = fmaf(w, ga.y, acc1);
        acc2 = fmaf(w, gb.x, acc2);
        acc3 = fmaf(w, gb.y, acc3);
    }
    if (k < cnt && side == 0) {           // leftover edge: lanes 0-15 only
        const int j = list[k];
        const uint2 hv = *reinterpret_cast<const uint2*>(
            g_half + j * (OUTF / 2) + sub * 2);
        const float srj = g_sr[j * HEADS + headp];
        float e = sl_h + srj;
        e = fmaxf(e, SLOPE * e);
        const float w = __expf(e);
        den += w;
        const float2 ga = __half22float2(*reinterpret_cast<const __half2*>(&hv.x));
        const float2 gb = __half22float2(*reinterpret_cast<const __half2*>(&hv.y));
        acc0 = fmaf(w, ga.x, acc0);
        acc1 = fmaf(w, ga.y, acc1);
        acc2 = fmaf(w, gb.x, acc2);
        acc3 = fmaf(w, gb.y, acc3);
    }

    // ---- Combine the two 16-lane sides, stash per-warp partials ----
    acc0 += __shfl_down_sync(0xFFFFFFFFu, acc0, 16);
    acc1 += __shfl_down_sync(0xFFFFFFFFu, acc1, 16);
    acc2 += __shfl_down_sync(0xFFFFFFFFu, acc2, 16);
    acc3 += __shfl_down_sync(0xFFFFFFFFu, acc3, 16);
    den  += __shfl_down_sync(0xFFFFFFFFu, den, 16);

    if (lane < 16) {
        part_acc[warp][sub * 4 + 0] = acc0;
        part_acc[warp][sub * 4 + 1] = acc1;
        part_acc[warp][sub * 4 + 2] = acc2;
        part_acc[warp][sub * 4 + 3] = acc3;
        if ((sub & 1) == 0) part_den[warp][headp] = den;
    }
    __syncthreads();

    // ---- Final: 128 threads cover 2 rows x 64 feats ----
    if (tid < 128) {
        const int r = tid >> 6;                  // row within block
        const int f = tid & 63;
        float s = 0.f, d = 0.f;
        const int hh = f >> 3;
        #pragma unroll
        for (int w4 = 0; w4 < 4; w4++) {
            s += part_acc[r * 4 + w4][f];
            d += part_den[r * 4 + w4][hh];
        }
        out[(size_t)(fb * 2 + r) * OUTF + f] = s / d;
    }

    // ---- Replay hygiene: last fused block resets counters ----
    if (tid == 0) {
        const int prev = atomicAdd(&g_fusedone, 1);
        if (prev == FUSE_BLOCKS - 1) {
            g_projdone = 0;
            g_fusedone = 0;
        }
    }
}

// ---------------------------------------------------------------------------
extern "C" void kernel_launch(void* const* d_in, const int* in_sizes, int n_in,
                              void* d_out, int out_size)
{
    const float*        h   = (const float*)d_in[0];
    const unsigned int* adj = (const unsigned int*)d_in[1];
    const float*        W   = (const float*)d_in[2];
    const float*        a_l = (const float*)d_in[3];
    const float*        a_r = (const float*)d_in[4];
    float*              out = (float*)d_out;

    fused_kernel<<<PROJ_BLOCKS + FUSE_BLOCKS, 256>>>(h, adj, W, a_l, a_r, out);
}

// round 16
// speedup vs baseline: 1.2323x; 1.1919x over previous
#include <cuda_runtime.h>
#include <cuda_fp16.h>
#include <cstdint>

#define N_NODES 4096
#define IN_F    128
#define HEADS   8
#define HIDDEN  8
#define OUTF    64   // HEADS*HIDDEN
#define SLOPE   0.2f
#define NODES_PER_PROJ 16
#define PROJ_BLOCKS (N_NODES / NODES_PER_PROJ)     // 256
#define COMP_BLOCKS 2048                            // 8 warps x 1024 words each
#define MAXEH   96            // max edges per half-row (Poisson(41), max ~75)

// Scratch (allocation-free rule: __device__ globals)
__device__ __half2 g_half[N_NODES * (OUTF / 2)];      // 512 KB fp16 features
__device__ float g_sl[N_NODES * HEADS];               // 128 KB
__device__ float g_sr[N_NODES * HEADS];               // 128 KB
__device__ unsigned int g_bits[N_NODES * N_NODES / 32]; // 2 MB bitmask (lane-packed order)

// ---------------------------------------------------------------------------
// Kernel 1 (merged): heterogeneous grid.
//   blocks [0, 256):    proj  g = h @ W + sl/sr head dots, g stored as fp16
//   blocks [256, 2304): compress 64 MB int32 adjacency -> 2 MB bitmask
// Static smem 12 KB so compress co-resides at 8 blocks/SM.
// Bitmask packing (ballot-free): g_bits[wg*32 + lane] bit (4c+wi) <->
//   node wg*1024 + c*128 + lane*4 + wi
// ---------------------------------------------------------------------------
__global__ void __launch_bounds__(256) prep_kernel(
    const float* __restrict__ h,
    const unsigned int* __restrict__ adj,
    const float* __restrict__ W,
    const float* __restrict__ a_l,
    const float* __restrict__ a_r)
{
    __shared__ float hs[NODES_PER_PROJ][IN_F];      // 8 KB
    __shared__ float gs[NODES_PER_PROJ][OUTF];      // 4 KB

    const int tid = threadIdx.x;

    if (blockIdx.x >= PROJ_BLOCKS) {
        // ------------------ compress path (ballot-free) ------------------
        const int lane = tid & 31;
        const size_t warp_global =
            ((size_t)(blockIdx.x - PROJ_BLOCKS) * 256 + tid) >> 5;
        const size_t word_base = warp_global * 1024;

        const uint4* p = reinterpret_cast<const uint4*>(adj) + word_base / 4;
        uint4 v[8];
        #pragma unroll
        for (int c = 0; c < 8; c++) v[c] = __ldcs(p + c * 32 + lane);

        unsigned w = 0u;
        #pragma unroll
        for (int c = 0; c < 8; c++) {
            w |= (v[c].x != 0u ? 1u : 0u) << (4 * c + 0);
            w |= (v[c].y != 0u ? 1u : 0u) << (4 * c + 1);
            w |= (v[c].z != 0u ? 1u : 0u) << (4 * c + 2);
            w |= (v[c].w != 0u ? 1u : 0u) << (4 * c + 3);
        }
        g_bits[warp_global * 32 + lane] = w;
        return;
    }

    // ------------------ proj path (W via L1, no smem staging) ------------
    const int node0 = blockIdx.x * NODES_PER_PROJ;

    for (int i = tid; i < NODES_PER_PROJ * IN_F; i += 256)
        hs[i >> 7][i & 127] = h[(size_t)node0 * IN_F + i];
    __syncthreads();

    const int c  = tid & 63;
    const int nb = (tid >> 6) * 4;
    float acc[4] = {0.f, 0.f, 0.f, 0.f};
    #pragma unroll 8
    for (int k = 0; k < IN_F; k++) {
        const float wv = __ldg(&W[k * OUTF + c]);
        acc[0] = fmaf(hs[nb + 0][k], wv, acc[0]);
        acc[1] = fmaf(hs[nb + 1][k], wv, acc[1]);
        acc[2] = fmaf(hs[nb + 2][k], wv, acc[2]);
        acc[3] = fmaf(hs[nb + 3][k], wv, acc[3]);
    }
    __half* gh = reinterpret_cast<__half*>(g_half);
    #pragma unroll
    for (int q = 0; q < 4; q++) {
        gh[(size_t)(node0 + nb + q) * OUTF + c] = __float2half(acc[q]);
        gs[nb + q][c] = acc[q];
    }
    __syncthreads();

    const int t = tid & 127;
    const int nl = t >> 3, hh = t & 7;
    const float* av = (tid < 128) ? a_l : a_r;
    float s = 0.f;
    #pragma unroll
    for (int d = 0; d < 8; d++) s = fmaf(gs[nl][hh * 8 + d], av[d], s);
    if (tid < 128) g_sl[(node0 + nl) * HEADS + hh] = s;
    else           g_sr[(node0 + nl) * HEADS + hh] = s;
}

// ---------------------------------------------------------------------------
// Kernel 2: TWO warps per row (8192 warps), each warp owns half the bitmask
// row (64 words = one uint2/lane, ~41 edges). Edge loop in 8-LANE GROUPS:
// 4 edges concurrently per warp, lane owns a whole head (uint4 = 4 half2),
// one exp per edge per head lane (zero duplication), x4 batched (16 edges,
// 8 loads in flight per lane). Epilogue: shfl_down(16)+shfl_down(8) ->
// lanes 0-7 hold head sums -> smem partials -> 4 rows/block writer.
// Decode (lane-packed bits): widx = half*64 + lane*2 + wi;
//   jb = (widx>>5)*1024 + (widx&31)*4;  j = jb + ((b>>2)<<7) + (b&3)
// Single-pass softmax exact (|e| < ~3 in fp32).
// ---------------------------------------------------------------------------
__global__ void __launch_bounds__(256) attn_kernel(float* __restrict__ out)
{
    __shared__ uint16_t lists[8][MAXEH];    // 1.5 KB
    __shared__ float part_acc[8][OUTF];     // 2 KB
    __shared__ float part_den[8][HEADS];    // 256 B

    const int warp = threadIdx.x >> 5;      // 0..7
    const int lane = threadIdx.x & 31;
    const int rloc = warp >> 1;             // row within block, 0..3
    const int half = warp & 1;              // which half of the row
    const int row  = blockIdx.x * 4 + rloc;

    uint16_t* list = lists[warp];
    const int grp = lane >> 3;              // 0..3: edge slot within warp
    const int hid = lane & 7;               // this lane's head
    const float sl_h = g_sl[row * HEADS + hid];

    // ---- Load half bitmask row (2 words/lane) and compact ----
    const uint2 mv = reinterpret_cast<const uint2*>(
        g_bits + row * 128 + half * 64)[lane];
    const int myc = __popc(mv.x) + __popc(mv.y);
    int off = myc;
    #pragma unroll
    for (int d = 1; d < 32; d <<= 1) {
        int n = __shfl_up_sync(0xFFFFFFFFu, off, d);
        if (lane >= d) off += n;
    }
    const int cnt = __shfl_sync(0xFFFFFFFFu, off, 31);
    off -= myc;                                  // exclusive prefix
    {
        unsigned ws[2] = {mv.x, mv.y};
        #pragma unroll
        for (int wi = 0; wi < 2; wi++) {
            unsigned m = ws[wi];
            const int widx = half * 64 + lane * 2 + wi;
            const int jb = (widx >> 5) * 1024 + (widx & 31) * 4;
            while (m) {
                const int b = __ffs(m) - 1;
                m &= m - 1;
                list[off++] = (uint16_t)(jb + ((b >> 2) << 7) + (b & 3));
            }
        }
    }
    __syncwarp();

    // ---- Edge loop: 16 edges per iteration (4 per 8-lane group) ----
    float acc[8];
    #pragma unroll
    for (int i = 0; i < 8; i++) acc[i] = 0.f;
    float den = 0.f;

    int k = 0;
    #pragma unroll 1
    for (; k + 16 <= cnt; k += 16) {
        int j[4];
        #pragma unroll
        for (int q = 0; q < 4; q++) j[q] = list[k + q * 4 + grp];
        uint4 hv[4];
        float sr[4];
        #pragma unroll
        for (int q = 0; q < 4; q++) {
            hv[q] = *reinterpret_cast<const uint4*>(
                g_half + j[q] * (OUTF / 2) + hid * 4);
            sr[q] = g_sr[j[q] * HEADS + hid];
        }
        #pragma unroll
        for (int q = 0; q < 4; q++) {
            float e = sl_h + sr[q];
            e = fmaxf(e, SLOPE * e);
            const float w = __expf(e);
            den += w;
            const __half2* hp = reinterpret_cast<const __half2*>(&hv[q]);
            #pragma unroll
            for (int t = 0; t < 4; t++) {
                const float2 g2 = __half22float2(hp[t]);
                acc[2 * t + 0] = fmaf(w, g2.x, acc[2 * t + 0]);
                acc[2 * t + 1] = fmaf(w, g2.y, acc[2 * t + 1]);
            }
        }
    }
    // ---- Tail: 4 edges at a time, groups predicated (no cross-lane ops) ----
    #pragma unroll 1
    for (; k < cnt; k += 4) {
        const int kk = k + grp;
        if (kk < cnt) {
            const int j = list[kk];
            const uint4 hv = *reinterpret_cast<const uint4*>(
                g_half + j * (OUTF / 2) + hid * 4);
            const float srj = g_sr[j * HEADS + hid];
            float e = sl_h + srj;
            e = fmaxf(e, SLOPE * e);
            const float w = __expf(e);
            den += w;
            const __half2* hp = reinterpret_cast<const __half2*>(&hv);
            #pragma unroll
            for (int t = 0; t < 4; t++) {
                const float2 g2 = __half22float2(hp[t]);
                acc[2 * t + 0] = fmaf(w, g2.x, acc[2 * t + 0]);
                acc[2 * t + 1] = fmaf(w, g2.y, acc[2 * t + 1]);
            }
        }
    }

    // ---- Combine the 4 groups: +16, +8 -> lanes 0..7 hold head sums ----
    #pragma unroll
    for (int i = 0; i < 8; i++) {
        acc[i] += __shfl_down_sync(0xFFFFFFFFu, acc[i], 16);
        acc[i] += __shfl_down_sync(0xFFFFFFFFu, acc[i], 8);
    }
    den += __shfl_down_sync(0xFFFFFFFFu, den, 16);
    den += __shfl_down_sync(0xFFFFFFFFu, den, 8);

    if (lane < 8) {
        #pragma unroll
        for (int i = 0; i < 8; i++) part_acc[warp][hid * 8 + i] = acc[i];
        part_den[warp][hid] = den;
    }
    __syncthreads();

    // ---- Final: 256 threads cover 4 rows x 64 feats ----
    {
        const int r = threadIdx.x >> 6;          // row within block
        const int f = threadIdx.x & 63;
        const float s = part_acc[2 * r][f] + part_acc[2 * r + 1][f];
        const int hh = f >> 3;
        const float d = part_den[2 * r][hh] + part_den[2 * r + 1][hh];
        out[(size_t)(blockIdx.x * 4 + r) * OUTF + f] = s / d;
    }
}

// ---------------------------------------------------------------------------
extern "C" void kernel_launch(void* const* d_in, const int* in_sizes, int n_in,
                              void* d_out, int out_size)
{
    const float*        h   = (const float*)d_in[0];
    const unsigned int* adj = (const unsigned int*)d_in[1];
    const float*        W   = (const float*)d_in[2];
    const float*        a_l = (const float*)d_in[3];
    const float*        a_r = (const float*)d_in[4];
    float*              out = (float*)d_out;

    prep_kernel<<<PROJ_BLOCKS + COMP_BLOCKS, 256>>>(h, adj, W, a_l, a_r);
    attn_kernel<<<N_NODES / 4, 256>>>(out);
}

// round 17
// speedup vs baseline: 1.2642x; 1.0259x over previous
#include <cuda_runtime.h>
#include <cuda_fp16.h>
#include <cstdint>

#define N_NODES 4096
#define IN_F    128
#define HEADS   8
#define HIDDEN  8
#define OUTF    64   // HEADS*HIDDEN
#define SLOPE   0.2f
#define NODES_PER_PROJ 16
#define PROJ_BLOCKS (N_NODES / NODES_PER_PROJ)     // 256
#define COMP_BLOCKS 2048                            // 8 warps x 1024 words each
#define MAXEH   96            // max edges per half-row (Poisson(41), max ~75)

// Scratch (allocation-free rule: __device__ globals)
__device__ __half2 g_half[N_NODES * (OUTF / 2)];      // 512 KB fp16 features
__device__ float g_sl[N_NODES * HEADS];               // 128 KB
__device__ float g_sr[N_NODES * HEADS];               // 128 KB
__device__ unsigned int g_bits[N_NODES * N_NODES / 32]; // 2 MB bitmask (lane-packed order)

// Packed f32x2 FMA (FFMA2 — reachable only via PTX on sm_103a)
#define FMA_F32X2(d, a, b, c) \
    asm("fma.rn.f32x2 %0, %1, %2, %3;" : "=l"(d) : "l"(a), "l"(b), "l"(c))
#define PACK_F32X2(out, lo, hi) \
    asm("mov.b64 %0, {%1, %2};" : "=l"(out) : "f"(lo), "f"(hi))
#define UNPACK_F32X2(lo, hi, in) \
    asm("mov.b64 {%0, %1}, %2;" : "=f"(lo), "=f"(hi) : "l"(in))

// ---------------------------------------------------------------------------
// Kernel 1 (merged): heterogeneous grid.
//   blocks [0, 256):    proj  g = h @ W + sl/sr head dots, g stored as fp16
//   blocks [256, 2304): compress 64 MB int32 adjacency -> 2 MB bitmask
// Static smem 12 KB so compress co-resides at 8 blocks/SM.
// Bitmask packing (ballot-free): g_bits[wg*32 + lane] bit (4c+wi) <->
//   node wg*1024 + c*128 + lane*4 + wi
// ---------------------------------------------------------------------------
__global__ void __launch_bounds__(256) prep_kernel(
    const float* __restrict__ h,
    const unsigned int* __restrict__ adj,
    const float* __restrict__ W,
    const float* __restrict__ a_l,
    const float* __restrict__ a_r)
{
    __shared__ float hs[NODES_PER_PROJ][IN_F];      // 8 KB
    __shared__ float gs[NODES_PER_PROJ][OUTF];      // 4 KB

    const int tid = threadIdx.x;

    if (blockIdx.x >= PROJ_BLOCKS) {
        // ------------------ compress path (ballot-free) ------------------
        const int lane = tid & 31;
        const size_t warp_global =
            ((size_t)(blockIdx.x - PROJ_BLOCKS) * 256 + tid) >> 5;
        const size_t word_base = warp_global * 1024;

        const uint4* p = reinterpret_cast<const uint4*>(adj) + word_base / 4;
        uint4 v[8];
        #pragma unroll
        for (int c = 0; c < 8; c++) v[c] = __ldcs(p + c * 32 + lane);

        unsigned w = 0u;
        #pragma unroll
        for (int c = 0; c < 8; c++) {
            w |= (v[c].x != 0u ? 1u : 0u) << (4 * c + 0);
            w |= (v[c].y != 0u ? 1u : 0u) << (4 * c + 1);
            w |= (v[c].z != 0u ? 1u : 0u) << (4 * c + 2);
            w |= (v[c].w != 0u ? 1u : 0u) << (4 * c + 3);
        }
        g_bits[warp_global * 32 + lane] = w;
        return;
    }

    // ------------------ proj path (W via L1, no smem staging) ------------
    const int node0 = blockIdx.x * NODES_PER_PROJ;

    for (int i = tid; i < NODES_PER_PROJ * IN_F; i += 256)
        hs[i >> 7][i & 127] = h[(size_t)node0 * IN_F + i];
    __syncthreads();

    const int c  = tid & 63;
    const int nb = (tid >> 6) * 4;
    float acc[4] = {0.f, 0.f, 0.f, 0.f};
    #pragma unroll 8
    for (int k = 0; k < IN_F; k++) {
        const float wv = __ldg(&W[k * OUTF + c]);
        acc[0] = fmaf(hs[nb + 0][k], wv, acc[0]);
        acc[1] = fmaf(hs[nb + 1][k], wv, acc[1]);
        acc[2] = fmaf(hs[nb + 2][k], wv, acc[2]);
        acc[3] = fmaf(hs[nb + 3][k], wv, acc[3]);
    }
    __half* gh = reinterpret_cast<__half*>(g_half);
    #pragma unroll
    for (int q = 0; q < 4; q++) {
        gh[(size_t)(node0 + nb + q) * OUTF + c] = __float2half(acc[q]);
        gs[nb + q][c] = acc[q];
    }
    __syncthreads();

    const int t = tid & 127;
    const int nl = t >> 3, hh = t & 7;
    const float* av = (tid < 128) ? a_l : a_r;
    float s = 0.f;
    #pragma unroll
    for (int d = 0; d < 8; d++) s = fmaf(gs[nl][hh * 8 + d], av[d], s);
    if (tid < 128) g_sl[(node0 + nl) * HEADS + hh] = s;
    else           g_sr[(node0 + nl) * HEADS + hh] = s;
}

// ---------------------------------------------------------------------------
// Kernel 2: 128-thread blocks, 2 rows per block (grid 2048; finer wave
// granularity + better Poisson balance). Two warps per row, each owns half
// the bitmask row (~41 edges). Edge loop in 8-LANE GROUPS: lane owns a whole
// head (uint4 = 4 half2), group owns 4 CONSECUTIVE edges per batch (16
// edges/warp-iteration). Accumulation via packed fma.rn.f32x2 (FFMA2):
// 4 FFMA2 + 1 w-pack per edge instead of 8 scalar FFMA.
// Decode (lane-packed bits): widx = half*64 + lane*2 + wi;
//   jb = (widx>>5)*1024 + (widx&31)*4;  j = jb + ((b>>2)<<7) + (b&3)
// Single-pass softmax exact (|e| < ~3 in fp32).
// ---------------------------------------------------------------------------
__global__ void __launch_bounds__(128) attn_kernel(float* __restrict__ out)
{
    __shared__ uint16_t lists[4][MAXEH];    // 768 B
    __shared__ float part_acc[4][OUTF];     // 1 KB
    __shared__ float part_den[4][HEADS];    // 128 B

    const int tid  = threadIdx.x;
    const int warp = tid >> 5;              // 0..3
    const int lane = tid & 31;
    const int rloc = warp >> 1;             // row within block, 0..1
    const int half = warp & 1;              // which half of the row
    const int row  = blockIdx.x * 2 + rloc;

    uint16_t* list = lists[warp];
    const int grp = lane >> 3;              // 0..3: edge slot within warp
    const int hid = lane & 7;               // this lane's head
    const float sl_h = g_sl[row * HEADS + hid];

    // ---- Load half bitmask row (2 words/lane) and compact ----
    const uint2 mv = reinterpret_cast<const uint2*>(
        g_bits + row * 128 + half * 64)[lane];
    const int myc = __popc(mv.x) + __popc(mv.y);
    int off = myc;
    #pragma unroll
    for (int d = 1; d < 32; d <<= 1) {
        int n = __shfl_up_sync(0xFFFFFFFFu, off, d);
        if (lane >= d) off += n;
    }
    const int cnt = __shfl_sync(0xFFFFFFFFu, off, 31);
    off -= myc;                                  // exclusive prefix
    {
        unsigned ws[2] = {mv.x, mv.y};
        #pragma unroll
        for (int wi = 0; wi < 2; wi++) {
            unsigned m = ws[wi];
            const int widx = half * 64 + lane * 2 + wi;
            const int jb = (widx >> 5) * 1024 + (widx & 31) * 4;
            while (m) {
                const int b = __ffs(m) - 1;
                m &= m - 1;
                list[off++] = (uint16_t)(jb + ((b >> 2) << 7) + (b & 3));
            }
        }
    }
    __syncwarp();

    // ---- Edge loop: 16 edges per iteration (4 consecutive per group) ----
    unsigned long long acc2[4] = {0ull, 0ull, 0ull, 0ull};
    float den = 0.f;

    int k = 0;
    #pragma unroll 1
    for (; k + 16 <= cnt; k += 16) {
        int j[4];
        #pragma unroll
        for (int q = 0; q < 4; q++) j[q] = list[k + grp * 4 + q];
        uint4 hv[4];
        float sr[4];
        #pragma unroll
        for (int q = 0; q < 4; q++) {
            hv[q] = *reinterpret_cast<const uint4*>(
                g_half + j[q] * (OUTF / 2) + hid * 4);
            sr[q] = g_sr[j[q] * HEADS + hid];
        }
        #pragma unroll
        for (int q = 0; q < 4; q++) {
            float e = sl_h + sr[q];
            e = fmaxf(e, SLOPE * e);
            const float w = __expf(e);
            den += w;
            unsigned long long wp;
            PACK_F32X2(wp, w, w);
            const __half2* hp = reinterpret_cast<const __half2*>(&hv[q]);
            #pragma unroll
            for (int t = 0; t < 4; t++) {
                const float2 g2 = __half22float2(hp[t]);
                unsigned long long gp;
                PACK_F32X2(gp, g2.x, g2.y);
                FMA_F32X2(acc2[t], wp, gp, acc2[t]);
            }
        }
    }
    // ---- Tail: 4 edges at a time, groups predicated ----
    #pragma unroll 1
    for (; k < cnt; k += 4) {
        const int kk = k + grp;
        if (kk < cnt) {
            const int j = list[kk];
            const uint4 hv = *reinterpret_cast<const uint4*>(
                g_half + j * (OUTF / 2) + hid * 4);
            const float srj = g_sr[j * HEADS + hid];
            float e = sl_h + srj;
            e = fmaxf(e, SLOPE * e);
            const float w = __expf(e);
            den += w;
            unsigned long long wp;
            PACK_F32X2(wp, w, w);
            const __half2* hp = reinterpret_cast<const __half2*>(&hv);
            #pragma unroll
            for (int t = 0; t < 4; t++) {
                const float2 g2 = __half22float2(hp[t]);
                unsigned long long gp;
                PACK_F32X2(gp, g2.x, g2.y);
                FMA_F32X2(acc2[t], wp, gp, acc2[t]);
            }
        }
    }

    // ---- Unpack, combine the 4 groups: +16, +8 -> lanes 0..7 ----
    float acc[8];
    #pragma unroll
    for (int t = 0; t < 4; t++) UNPACK_F32X2(acc[2 * t], acc[2 * t + 1], acc2[t]);
    #pragma unroll
    for (int i = 0; i < 8; i++) {
        acc[i] += __shfl_down_sync(0xFFFFFFFFu, acc[i], 16);
        acc[i] += __shfl_down_sync(0xFFFFFFFFu, acc[i], 8);
    }
    den += __shfl_down_sync(0xFFFFFFFFu, den, 16);
    den += __shfl_down_sync(0xFFFFFFFFu, den, 8);

    if (lane < 8) {
        #pragma unroll
        for (int i = 0; i < 8; i++) part_acc[warp][hid * 8 + i] = acc[i];
        part_den[warp][hid] = den;
    }
    __syncthreads();

    // ---- Final: 128 threads cover 2 rows x 64 feats ----
    {
        const int r = tid >> 6;                  // row within block
        const int f = tid & 63;
        const float s = part_acc[2 * r][f] + part_acc[2 * r + 1][f];
        const int hh = f >> 3;
        const float d = part_den[2 * r][hh] + part_den[2 * r + 1][hh];
        out[(size_t)(blockIdx.x * 2 + r) * OUTF + f] = s / d;
    }
}

// ---------------------------------------------------------------------------
extern "C" void kernel_launch(void* const* d_in, const int* in_sizes, int n_in,
                              void* d_out, int out_size)
{
    const float*        h   = (const float*)d_in[0];
    const unsigned int* adj = (const unsigned int*)d_in[1];
    const float*        W   = (const float*)d_in[2];
    const float*        a_l = (const float*)d_in[3];
    const float*        a_r = (const float*)d_in[4];
    float*              out = (float*)d_out;

    prep_kernel<<<PROJ_BLOCKS + COMP_BLOCKS, 256>>>(h, adj, W, a_l, a_r);
    attn_kernel<<<N_NODES / 2, 128>>>(out);
}